// round 16
// baseline (speedup 1.0000x reference)
#include <cuda_runtime.h>
#include <cuda_fp16.h>
#include <cstdint>
#include <cstddef>

#define NB 4
#define HH 256
#define WW 256
#define CC 96
#define NF 4
#define CT 32                   // channels per CTA
#define NCB (CC / CT)           // 3 channel blocks
#define NJ 16                   // chunks per row/column
#define CL 16                   // chunk length
#define NTHR 512                // NJ * CT

// compile-time filter coefficient powers (guaranteed immediates)
template<int F> struct FA { static constexpr float v = (F==0)?0.1f:(F==1)?0.3f:(F==2)?0.4f:0.8f; };
template<int F, int E> struct PW { static constexpr float v = PW<F,E-1>::v * FA<F>::v; };
template<int F> struct PW<F,0> { static constexpr float v = 1.0f; };

__constant__ float c_a[NF]   = {0.1f, 0.3f, 0.4f, 0.8f};
__constant__ float c_cf[NF]  = {0.81818181818f, 0.53846153846f, 0.42857142857f, 0.11111111111f}; // (1-a)/(1+a)
__constant__ float c_i1m[NF] = {1.11111111111f, 1.42857142857f, 1.66666666667f, 5.0f};           // 1/(1-a)
__constant__ float c_A16[NF] = {1.0e-16f, 4.3046721e-9f, 4.2949673e-7f, 2.8147498e-2f};          // a^16

// intermediate: [f][n][cblk][w][h][c32]
#define COLSZ ((size_t)HH * CT)
__device__ __half g_mid[(size_t)NF * NB * NCB * WW * COLSZ];
__device__ __forceinline__ size_t mid_base(int f, int n, int cblk) {
    return (((size_t)f * NB + n) * NCB + cblk) * ((size_t)WW * COLSZ);
}

// producer->consumer progress counters, one per (n, cblk) group
__device__ int g_cnt[NB * NCB];

// parallel carry-correction epilogue: Y[i] += a^{i+1}*u + a^{16-i}*v  (immediates)
template<int F>
__device__ __forceinline__ void epi_add(float u, float v, float* __restrict__ Y) {
#define EPI(i) Y[i] = fmaf(PW<F,(i)+1>::v, u, fmaf(PW<F,CL-(i)>::v, v, Y[i]));
    EPI(0)  EPI(1)  EPI(2)  EPI(3)  EPI(4)  EPI(5)  EPI(6)  EPI(7)
    EPI(8)  EPI(9)  EPI(10) EPI(11) EPI(12) EPI(13) EPI(14) EPI(15)
#undef EPI
}

// ---------------------------------------------------------------------------
__global__ void init_k() {
    if (threadIdx.x < NB * NCB) g_cnt[threadIdx.x] = 0;
}

// ---------------------------------------------------------------------------
// Fused kernel. CTA role by blockIdx.y: y<HH -> horizontal row y;
// y>=HH -> vertical column (y-HH), gated on all 256 h-CTAs of (n,cblk).
// Dispatch order per batch: 768 h-CTAs then 768 v-CTAs -> v(n) overlaps h(n+1).
// ---------------------------------------------------------------------------
__global__ void __launch_bounds__(NTHR, 2) fused_k(const float* __restrict__ x,
                                                   float* __restrict__ out,
                                                   const float* __restrict__ gl) {
    const int cblk = blockIdx.x;
    const int yy   = blockIdx.y;
    const int n    = blockIdx.z;

    __shared__ float Ls  [NF][NJ][CT];
    __shared__ float LBs [NF][NJ][CT];
    __shared__ float cinS[NF][NJ][CT];
    __shared__ float ginS[NF][NJ][CT];
    __shared__ float X0s [NF][CT];

    const int tid = threadIdx.x;
    const int c = tid & 31;
    const int j = tid >> 5;

    if (yy < HH) {
        // =================== horizontal role (row h = yy) ===================
        const int h = yy;

        float xv[CL];
        {
            const float* xp = x + (((size_t)(n * HH + h)) * WW + j * CL) * CC
                            + cblk * CT + c;
            #pragma unroll
            for (int i = 0; i < CL; ++i) xv[i] = xp[(size_t)i * CC];
        }

        // zero-carry tails for all 4 filters in one pass
        {
            float Lf0 = 0.f, Lf1 = 0.f, Lf2 = 0.f, Lf3 = 0.f;
            float Bf0 = 0.f, Bf1 = 0.f, Bf2 = 0.f, Bf3 = 0.f;
            #pragma unroll
            for (int i = 0; i < CL; ++i) {
                float xf = xv[i], xb = xv[CL - 1 - i];
                Lf0 = fmaf(c_a[0], Lf0, xf);  Bf0 = fmaf(c_a[0], Bf0, xb);
                Lf1 = fmaf(c_a[1], Lf1, xf);  Bf1 = fmaf(c_a[1], Bf1, xb);
                Lf2 = fmaf(c_a[2], Lf2, xf);  Bf2 = fmaf(c_a[2], Bf2, xb);
                Lf3 = fmaf(c_a[3], Lf3, xf);  Bf3 = fmaf(c_a[3], Bf3, xb);
            }
            Ls[0][j][c] = Lf0;  LBs[0][j][c] = Bf0;
            Ls[1][j][c] = Lf1;  LBs[1][j][c] = Bf1;
            Ls[2][j][c] = Lf2;  LBs[2][j][c] = Bf2;
            Ls[3][j][c] = Lf3;  LBs[3][j][c] = Bf3;
            if (j == 0) X0s[0][c] = xv[0];
        }
        __syncthreads();

        // dedup Horner: warp f computes filter-f carry chain once per channel
        if (j < NF) {
            const int f = j;
            const float A16 = c_A16[f];
            float p = X0s[0][c] * c_i1m[f];
            #pragma unroll
            for (int m = 0; m < NJ; ++m) {
                cinS[f][m][c] = p;
                p = fmaf(A16, p, Ls[f][m][c]);
            }
            float q = p;
            #pragma unroll
            for (int m = NJ - 1; m >= 0; --m) {
                ginS[f][m][c] = q;
                q = fmaf(A16, q, LBs[f][m][c]);
            }
        }
        __syncthreads();

        // per-filter recompute with true carries + direct fp16 store
        #pragma unroll
        for (int f = 0; f < NF; ++f) {
            const float a  = c_a[f];
            const float cf = c_cf[f];
            float tf = cinS[f][j][c];
            float tb = ginS[f][j][c];
            float Yv[CL];
            #pragma unroll
            for (int k = 0; k < CL; ++k) {
                const int ib = CL - 1 - k;
                tf = fmaf(a, tf, xv[k]);
                tb = fmaf(a, tb, xv[ib]);
                if (k < CL / 2) {
                    Yv[k]  = tf;
                    Yv[ib] = tb - xv[ib];
                } else {
                    Yv[k]  += tf;
                    Yv[ib] += tb - xv[ib];
                }
            }
            __half* mp = g_mid + mid_base(f, n, cblk)
                       + (size_t)(j * CL) * COLSZ + (size_t)h * CT + c;
            #pragma unroll
            for (int k = 0; k < CL; ++k)
                mp[(size_t)k * COLSZ] = __float2half(cf * Yv[k]);
        }

        // signal completion of this row for group (n, cblk)
        __syncthreads();
        if (tid == 0) {
            __threadfence();
            atomicAdd(&g_cnt[n * NCB + cblk], 1);
        }
    } else {
        // ==================== vertical role (column w) ====================
        const int w = yy - HH;

        // wait until all 256 h rows of this (n, cblk) group are published
        if (tid == 0) {
            volatile int* p = &g_cnt[n * NCB + cblk];
            while (*p < HH) __nanosleep(128);
            __threadfence();
        }
        __syncthreads();

        // per-thread softmax weights (wt_f = softmax_f(c) * cf_f)
        float wt[NF];
        {
            const int cg = cblk * CT + c;
            float v0 = gl[0 * CC + cg], v1 = gl[1 * CC + cg];
            float v2 = gl[2 * CC + cg], v3 = gl[3 * CC + cg];
            float m = fmaxf(fmaxf(v0, v1), fmaxf(v2, v3));
            float e0 = __expf(v0 - m), e1 = __expf(v1 - m);
            float e2 = __expf(v2 - m), e3 = __expf(v3 - m);
            float r = __fdividef(1.0f, e0 + e1 + e2 + e3);
            wt[0] = e0 * r * c_cf[0];
            wt[1] = e1 * r * c_cf[1];
            wt[2] = e2 * r * c_cf[2];
            wt[3] = e3 * r * c_cf[3];
        }

        float Ysum[CL];
        #pragma unroll
        for (int i = 0; i < CL; ++i) Ysum[i] = 0.0f;

        // phase 1: fused zero-carry pass per filter (accumulate wt*S + tails)
        #pragma unroll
        for (int f = 0; f < NF; ++f) {
            const float a  = c_a[f];
            const float wf = wt[f];

            float xv[CL];
            {
                const __half* mp = g_mid + mid_base(f, n, cblk)
                                 + ((size_t)w * HH + j * CL) * CT + c;
                #pragma unroll
                for (int i = 0; i < CL; ++i)
                    xv[i] = __half2float(mp[(size_t)i * CT]);
            }

            float tf = 0.0f, tb = 0.0f;
            #pragma unroll
            for (int k = 0; k < CL; ++k) {
                const int ib = CL - 1 - k;
                tf = fmaf(a, tf, xv[k]);
                tb = fmaf(a, tb, xv[ib]);
                Ysum[k]  = fmaf(wf, tf, Ysum[k]);
                Ysum[ib] = fmaf(wf, tb - xv[ib], Ysum[ib]);
            }
            Ls [f][j][c] = tf;
            LBs[f][j][c] = tb;
            if (j == 0) X0s[f][c] = xv[0];
        }
        __syncthreads();

        // dedup Horner (warps 0-3)
        if (j < NF) {
            const int f = j;
            const float A16 = c_A16[f];
            float p = X0s[f][c] * c_i1m[f];
            #pragma unroll
            for (int m = 0; m < NJ; ++m) {
                cinS[f][m][c] = p;
                p = fmaf(A16, p, Ls[f][m][c]);
            }
            float q = p;
            #pragma unroll
            for (int m = NJ - 1; m >= 0; --m) {
                ginS[f][m][c] = q;
                q = fmaf(A16, q, LBs[f][m][c]);
            }
        }
        __syncthreads();

        // parallel carry correction (immediate powers)
        epi_add<0>(wt[0] * cinS[0][j][c], wt[0] * ginS[0][j][c], Ysum);
        epi_add<1>(wt[1] * cinS[1][j][c], wt[1] * ginS[1][j][c], Ysum);
        epi_add<2>(wt[2] * cinS[2][j][c], wt[2] * ginS[2][j][c], Ysum);
        epi_add<3>(wt[3] * cinS[3][j][c], wt[3] * ginS[3][j][c], Ysum);

        // output: full 128B-line stores straight from registers
        {
            float* ob = out + ((size_t)(n * HH + j * CL) * WW + w) * CC
                      + cblk * CT + c;
            #pragma unroll
            for (int i = 0; i < CL; ++i)
                ob[(size_t)i * WW * CC] = Ysum[i];
        }
    }
}

// ---------------------------------------------------------------------------
extern "C" void kernel_launch(void* const* d_in, const int* in_sizes, int n_in,
                              void* d_out, int out_size) {
    const float* x  = (const float*)d_in[0];
    const float* gl = (const float*)d_in[1];
    float* out = (float*)d_out;

    init_k<<<1, 32>>>();

    dim3 g(NCB, 2 * HH, NB);
    fused_k<<<g, NTHR>>>(x, out, gl);

    (void)in_sizes; (void)n_in; (void)out_size;
}

// round 17
// speedup vs baseline: 1.1028x; 1.1028x over previous
#include <cuda_runtime.h>
#include <cuda_fp16.h>
#include <cstdint>
#include <cstddef>

#define NB 4
#define HH 256
#define WW 256
#define CC 96
#define NF 4
#define CT 32                   // channels per CTA
#define NCB (CC / CT)           // 3 channel blocks
#define NJ 16                   // chunks per row/column
#define CL 16                   // chunk length
#define NTHR 512                // NJ * CT

// compile-time filter coefficient powers (guaranteed immediates)
template<int F> struct FA { static constexpr float v = (F==0)?0.1f:(F==1)?0.3f:(F==2)?0.4f:0.8f; };
template<int F, int E> struct PW { static constexpr float v = PW<F,E-1>::v * FA<F>::v; };
template<int F> struct PW<F,0> { static constexpr float v = 1.0f; };

__constant__ float c_a[NF]   = {0.1f, 0.3f, 0.4f, 0.8f};
__constant__ float c_cf[NF]  = {0.81818181818f, 0.53846153846f, 0.42857142857f, 0.11111111111f}; // (1-a)/(1+a)
__constant__ float c_i1m[NF] = {1.11111111111f, 1.42857142857f, 1.66666666667f, 5.0f};           // 1/(1-a)
__constant__ float c_A16[NF] = {1.0e-16f, 4.3046721e-9f, 4.2949673e-7f, 2.8147498e-2f};          // a^16

// intermediate: [f][n][cblk][w][h][c32]
#define COLSZ ((size_t)HH * CT)
__device__ __half g_mid[(size_t)NF * NB * NCB * WW * COLSZ];
__device__ __forceinline__ size_t mid_base(int f, int n, int cblk) {
    return (((size_t)f * NB + n) * NCB + cblk) * ((size_t)WW * COLSZ);
}

// parallel carry-correction epilogue: Y[i] += a^{i+1}*u + a^{16-i}*v  (immediates)
template<int F>
__device__ __forceinline__ void epi_add(float u, float v, float* __restrict__ Y) {
#define EPI(i) Y[i] = fmaf(PW<F,(i)+1>::v, u, fmaf(PW<F,CL-(i)>::v, v, Y[i]));
    EPI(0)  EPI(1)  EPI(2)  EPI(3)  EPI(4)  EPI(5)  EPI(6)  EPI(7)
    EPI(8)  EPI(9)  EPI(10) EPI(11) EPI(12) EPI(13) EPI(14) EPI(15)
#undef EPI
}

// ---------------------------------------------------------------------------
// K1: horizontal pass for batch n. CTA = (cblk, h). (R15 body, batch-split.)
// ---------------------------------------------------------------------------
__global__ void __launch_bounds__(NTHR, 2) hscan_k(const float* __restrict__ x,
                                                   int n) {
    const int cblk = blockIdx.x, h = blockIdx.y;

    __shared__ float Ls  [NF][NJ][CT];
    __shared__ float LBs [NF][NJ][CT];
    __shared__ float cinS[NF][NJ][CT];
    __shared__ float ginS[NF][NJ][CT];
    __shared__ float X0s[CT];

    const int tid = threadIdx.x;
    const int c = tid & 31;
    const int j = tid >> 5;

    float xv[CL];
    {
        const float* xp = x + (((size_t)(n * HH + h)) * WW + j * CL) * CC
                        + cblk * CT + c;
        #pragma unroll
        for (int i = 0; i < CL; ++i) xv[i] = xp[(size_t)i * CC];
    }

    // zero-carry tails for all 4 filters in one pass (8 chains, high ILP)
    {
        float Lf0 = 0.f, Lf1 = 0.f, Lf2 = 0.f, Lf3 = 0.f;
        float Bf0 = 0.f, Bf1 = 0.f, Bf2 = 0.f, Bf3 = 0.f;
        #pragma unroll
        for (int i = 0; i < CL; ++i) {
            float xf = xv[i], xb = xv[CL - 1 - i];
            Lf0 = fmaf(c_a[0], Lf0, xf);  Bf0 = fmaf(c_a[0], Bf0, xb);
            Lf1 = fmaf(c_a[1], Lf1, xf);  Bf1 = fmaf(c_a[1], Bf1, xb);
            Lf2 = fmaf(c_a[2], Lf2, xf);  Bf2 = fmaf(c_a[2], Bf2, xb);
            Lf3 = fmaf(c_a[3], Lf3, xf);  Bf3 = fmaf(c_a[3], Bf3, xb);
        }
        Ls[0][j][c] = Lf0;  LBs[0][j][c] = Bf0;
        Ls[1][j][c] = Lf1;  LBs[1][j][c] = Bf1;
        Ls[2][j][c] = Lf2;  LBs[2][j][c] = Bf2;
        Ls[3][j][c] = Lf3;  LBs[3][j][c] = Bf3;
        if (j == 0) X0s[c] = xv[0];
    }
    __syncthreads();

    // dedup Horner: warp f computes filter-f carry chain once per channel
    if (j < NF) {
        const int f = j;
        const float A16 = c_A16[f];
        float p = X0s[c] * c_i1m[f];
        #pragma unroll
        for (int m = 0; m < NJ; ++m) {
            cinS[f][m][c] = p;
            p = fmaf(A16, p, Ls[f][m][c]);
        }
        float q = p;
        #pragma unroll
        for (int m = NJ - 1; m >= 0; --m) {
            ginS[f][m][c] = q;
            q = fmaf(A16, q, LBs[f][m][c]);
        }
    }
    __syncthreads();

    // per-filter recompute with true carries + direct fp16 store
    #pragma unroll
    for (int f = 0; f < NF; ++f) {
        const float a  = c_a[f];
        const float cf = c_cf[f];
        float tf = cinS[f][j][c];
        float tb = ginS[f][j][c];
        float Yv[CL];
        #pragma unroll
        for (int k = 0; k < CL; ++k) {
            const int ib = CL - 1 - k;
            tf = fmaf(a, tf, xv[k]);
            tb = fmaf(a, tb, xv[ib]);
            if (k < CL / 2) {
                Yv[k]  = tf;
                Yv[ib] = tb - xv[ib];
            } else {
                Yv[k]  += tf;
                Yv[ib] += tb - xv[ib];
            }
        }
        __half* mp = g_mid + mid_base(f, n, cblk)
                   + (size_t)(j * CL) * COLSZ + (size_t)h * CT + c;
        #pragma unroll
        for (int k = 0; k < CL; ++k)
            mp[(size_t)k * COLSZ] = __float2half(cf * Yv[k]);
    }
}

// ---------------------------------------------------------------------------
// K2: vertical pass for batch n. CTA = (cblk, w). (R15 body, batch-split.)
// ---------------------------------------------------------------------------
__global__ void __launch_bounds__(NTHR, 2) vscan_k(float* __restrict__ out,
                                                   const float* __restrict__ gl,
                                                   int n) {
    const int cblk = blockIdx.x, w = blockIdx.y;

    __shared__ float Ls  [NF][NJ][CT];
    __shared__ float LBs [NF][NJ][CT];
    __shared__ float cinS[NF][NJ][CT];
    __shared__ float ginS[NF][NJ][CT];
    __shared__ float X0s[NF][CT];

    const int tid = threadIdx.x;
    const int c = tid & 31;
    const int j = tid >> 5;

    float wt[NF];
    {
        const int cg = cblk * CT + c;
        float v0 = gl[0 * CC + cg], v1 = gl[1 * CC + cg];
        float v2 = gl[2 * CC + cg], v3 = gl[3 * CC + cg];
        float m = fmaxf(fmaxf(v0, v1), fmaxf(v2, v3));
        float e0 = __expf(v0 - m), e1 = __expf(v1 - m);
        float e2 = __expf(v2 - m), e3 = __expf(v3 - m);
        float r = __fdividef(1.0f, e0 + e1 + e2 + e3);
        wt[0] = e0 * r * c_cf[0];
        wt[1] = e1 * r * c_cf[1];
        wt[2] = e2 * r * c_cf[2];
        wt[3] = e3 * r * c_cf[3];
    }

    float Ysum[CL];
    #pragma unroll
    for (int i = 0; i < CL; ++i) Ysum[i] = 0.0f;

    // phase 1: per filter, fused zero-carry pass (accumulates wt*S, yields tails)
    #pragma unroll
    for (int f = 0; f < NF; ++f) {
        const float a  = c_a[f];
        const float wf = wt[f];

        float xv[CL];
        {
            const __half* mp = g_mid + mid_base(f, n, cblk)
                             + ((size_t)w * HH + j * CL) * CT + c;
            #pragma unroll
            for (int i = 0; i < CL; ++i)
                xv[i] = __half2float(mp[(size_t)i * CT]);
        }

        float tf = 0.0f, tb = 0.0f;
        #pragma unroll
        for (int k = 0; k < CL; ++k) {
            const int ib = CL - 1 - k;
            tf = fmaf(a, tf, xv[k]);
            tb = fmaf(a, tb, xv[ib]);
            Ysum[k]  = fmaf(wf, tf, Ysum[k]);
            Ysum[ib] = fmaf(wf, tb - xv[ib], Ysum[ib]);
        }
        Ls [f][j][c] = tf;
        LBs[f][j][c] = tb;
        if (j == 0) X0s[f][c] = xv[0];
    }
    __syncthreads();

    // dedup Horner (warps 0-3, one filter each)
    if (j < NF) {
        const int f = j;
        const float A16 = c_A16[f];
        float p = X0s[f][c] * c_i1m[f];
        #pragma unroll
        for (int m = 0; m < NJ; ++m) {
            cinS[f][m][c] = p;
            p = fmaf(A16, p, Ls[f][m][c]);
        }
        float q = p;
        #pragma unroll
        for (int m = NJ - 1; m >= 0; --m) {
            ginS[f][m][c] = q;
            q = fmaf(A16, q, LBs[f][m][c]);
        }
    }
    __syncthreads();

    // parallel carry correction (immediate powers)
    epi_add<0>(wt[0] * cinS[0][j][c], wt[0] * ginS[0][j][c], Ysum);
    epi_add<1>(wt[1] * cinS[1][j][c], wt[1] * ginS[1][j][c], Ysum);
    epi_add<2>(wt[2] * cinS[2][j][c], wt[2] * ginS[2][j][c], Ysum);
    epi_add<3>(wt[3] * cinS[3][j][c], wt[3] * ginS[3][j][c], Ysum);

    // output: full 128B-line stores straight from registers
    {
        float* ob = out + ((size_t)(n * HH + j * CL) * WW + w) * CC + cblk * CT + c;
        #pragma unroll
        for (int i = 0; i < CL; ++i)
            ob[(size_t)i * WW * CC] = Ysum[i];
    }
}

// ---------------------------------------------------------------------------
// Two-stream software pipeline: h(n) on sA, v(n) on sB gated by event(h(n)).
// v(n) overlaps h(n+1); graph capture turns record/wait into dependency edges.
// Streams/events are created once (first, non-captured call) and reused.
// ---------------------------------------------------------------------------
extern "C" void kernel_launch(void* const* d_in, const int* in_sizes, int n_in,
                              void* d_out, int out_size) {
    const float* x  = (const float*)d_in[0];
    const float* gl = (const float*)d_in[1];
    float* out = (float*)d_out;

    static cudaStream_t sA = nullptr, sB = nullptr;
    static cudaEvent_t evRoot, evH[NB], evA, evB;
    if (sA == nullptr) {
        cudaStreamCreateWithFlags(&sA, cudaStreamNonBlocking);
        cudaStreamCreateWithFlags(&sB, cudaStreamNonBlocking);
        cudaEventCreateWithFlags(&evRoot, cudaEventDisableTiming);
        for (int n = 0; n < NB; ++n)
            cudaEventCreateWithFlags(&evH[n], cudaEventDisableTiming);
        cudaEventCreateWithFlags(&evA, cudaEventDisableTiming);
        cudaEventCreateWithFlags(&evB, cudaEventDisableTiming);
    }

    dim3 g1(NCB, HH, 1);
    dim3 g2(NCB, WW, 1);

    // fork from the (captured) default stream
    cudaEventRecord(evRoot, 0);
    cudaStreamWaitEvent(sA, evRoot, 0);
    cudaStreamWaitEvent(sB, evRoot, 0);

    for (int n = 0; n < NB; ++n) {
        hscan_k<<<g1, NTHR, 0, sA>>>(x, n);
        cudaEventRecord(evH[n], sA);
        cudaStreamWaitEvent(sB, evH[n], 0);
        vscan_k<<<g2, NTHR, 0, sB>>>(out, gl, n);
    }

    // join both streams back into the default stream
    cudaEventRecord(evA, sA);
    cudaEventRecord(evB, sB);
    cudaStreamWaitEvent(0, evA, 0);
    cudaStreamWaitEvent(0, evB, 0);

    (void)in_sizes; (void)n_in; (void)out_size;
}